// round 11
// baseline (speedup 1.0000x reference)
#include <cuda_runtime.h>

// ---------------------------------------------------------------------------
// MambaSSM: B=2, L=384, d_inner=384, d_state=384, dt_rank=384, d_conv=4
//
// Algebraic restructure:
//   Bm = (x@B_w^T)@B_w^T = x@(B_w@B_w)^T =: x@G_B^T
//   Cm = (x@B_w^T)@C_w^T = x@(C_w@B_w)^T =: x@G_C^T
// so dt, Bm, Cm all depend only on x -> one fused GEMM launch.
//
//   prep (grid 6,13,3): G_Bp[z][n][k] = sum_{s in chunk z} B_w[n][s]B_w[s][k]
//                       G_Cp likewise with C_w;  by==12 row: conv+silu -> g_U,
//                       g_SC[..].z = u*D[d]
//   main (grid 12,18):  grp0: dt=softplus(x@dt_w^T+b) -> g_SC .x,.y (uses g_U)
//                       grp1: Bm = x@(ΣG_Bp)^T -> g_BM
//                       grp2: Cm = x@(ΣG_Cp)^T -> g_CM
//   scan v5 (proven, unchanged).
// ---------------------------------------------------------------------------

#define LOG2E 1.4426950408889634f

__device__ float  g_GBp[3][384 * 384];
__device__ float  g_GCp[3][384 * 384];
__device__ float  g_U  [768 * 384];    // silu(conv(x))
__device__ float  g_BM [768 * 384];
__device__ float  g_CM [768 * 384];
__device__ float4 g_SC [768 * 384];    // (dt, dt*u, u*D, -)

__device__ __forceinline__ float ex2f(float x) {
    float y;
    asm("ex2.approx.ftz.f32 %0, %1;" : "=f"(y) : "f"(x));
    return y;
}

// ---------------------------------------------------------------------------
// prep: G_B/G_C split-K partials + fused conv/silu.
// G[n][k] = sum_s Aw[n][s] * B_w[s][k].  Tiles 64(n) x 64(k), s-chunk 128.
// ---------------------------------------------------------------------------
__global__ __launch_bounds__(256) void prep_kernel(
    const float* __restrict__ x,
    const float* __restrict__ B_w,
    const float* __restrict__ C_w,
    const float* __restrict__ convw,
    const float* __restrict__ convb,
    const float* __restrict__ Dvec)
{
    const int tid = threadIdx.x;

    if (blockIdx.y == 12) {
        // ---- conv + silu: 18 blocks x 256 threads = 4608 = 768ch x 6 segs ----
        const int t   = (blockIdx.z * 6 + blockIdx.x) * 256 + tid;
        const int ch  = t / 6;              // 0..767  (b*384+d)
        const int seg = t - ch * 6;
        const int b   = ch / 384;
        const int d   = ch - b * 384;
        const int l0  = seg * 64;

        const float c0 = convw[d * 4 + 0];
        const float c1 = convw[d * 4 + 1];
        const float c2 = convw[d * 4 + 2];
        const float c3 = convw[d * 4 + 3];
        const float cb = convb[d];
        const float Dd = Dvec[d];

        const float* xb = x + b * 147456 + d;
        float* up  = g_U + ch * 384;
        float* scz = (float*)(g_SC + ch * 384) + 2;   // .z component

        float w0 = (l0 >= 3) ? xb[(l0 - 3) * 384] : 0.f;
        float w1 = (l0 >= 2) ? xb[(l0 - 2) * 384] : 0.f;
        float w2 = (l0 >= 1) ? xb[(l0 - 1) * 384] : 0.f;

        for (int i = 0; i < 64; ++i) {
            const int l = l0 + i;
            const float w3 = xb[l * 384];
            float v = fmaf(w0, c0, fmaf(w1, c1, fmaf(w2, c2, fmaf(w3, c3, cb))));
            const float u = v / (1.f + expf(-v));      // silu
            up[l] = u;
            scz[l * 4] = u * Dd;
            w0 = w1; w1 = w2; w2 = w3;
        }
        return;
    }

    // ---- G gemm: output tile (n0, k0), s-chunk z ----
    __shared__ float As[16][64];   // [s][n]
    __shared__ float Bs[16][64];   // [s][k]

    const int n0  = blockIdx.x * 64;
    const bool isC = (blockIdx.y >= 6);
    const int k0  = (isC ? blockIdx.y - 6 : blockIdx.y) * 64;
    const int z   = blockIdx.z;
    const int s0  = z * 128;
    const float* Aw = isC ? C_w : B_w;
    float* Gp = isC ? g_GCp[z] : g_GBp[z];

    const int rowA = tid >> 2;            // n: 0..63
    const int colA = (tid & 3) << 2;      // s: 0,4,8,12
    const int srow = tid >> 4;            // s: 0..15
    const int kcol = (tid & 15) << 2;     // k: 0..60

    const float* Ap = Aw  + (n0 + rowA) * 384 + s0 + colA;
    const float* Bp = B_w + (s0 + srow) * 384 + k0 + kcol;

    float4 aR = *(const float4*)Ap;
    float4 bR = *(const float4*)Bp;

    float acc[4][4];
#pragma unroll
    for (int i = 0; i < 4; i++)
#pragma unroll
        for (int j = 0; j < 4; j++) acc[i][j] = 0.f;

    const int tx = tid & 15;
    const int ty = tid >> 4;

    for (int st = 0; st < 8; ++st) {
        As[colA + 0][rowA] = aR.x;
        As[colA + 1][rowA] = aR.y;
        As[colA + 2][rowA] = aR.z;
        As[colA + 3][rowA] = aR.w;
        *(float4*)&Bs[srow][kcol] = bR;
        __syncthreads();

        if (st < 7) {
            aR = *(const float4*)(Ap + (st + 1) * 16);
            bR = *(const float4*)(Bp + (st + 1) * 16 * 384);
        }

#pragma unroll
        for (int s = 0; s < 16; ++s) {
            float4 av = *(const float4*)&As[s][ty << 2];
            float4 bv = *(const float4*)&Bs[s][tx << 2];
            float a[4] = {av.x, av.y, av.z, av.w};
            float b[4] = {bv.x, bv.y, bv.z, bv.w};
#pragma unroll
            for (int i = 0; i < 4; i++)
#pragma unroll
                for (int j = 0; j < 4; j++)
                    acc[i][j] = fmaf(a[i], b[j], acc[i][j]);
        }
        __syncthreads();
    }

#pragma unroll
    for (int i = 0; i < 4; i++)
#pragma unroll
        for (int j = 0; j < 4; j++)
            Gp[(n0 + (ty << 2) + i) * 384 + k0 + (tx << 2) + j] = acc[i][j];
}

// ---------------------------------------------------------------------------
// main: C[m,n] = sum_k x[m,k] * W[n,k].  grid (12, 18), 64x64 tiles.
// grp0 (bn<6): W=dt_w, epilogue softplus + sc pack.
// grp1: W=ΣG_Bp -> g_BM.  grp2: W=ΣG_Cp -> g_CM.
// ---------------------------------------------------------------------------
__global__ __launch_bounds__(256) void main_gemm(
    const float* __restrict__ x,
    const float* __restrict__ dt_w,
    const float* __restrict__ dt_b)
{
    __shared__ float As[16][64];
    __shared__ float Bs[16][64];

    const int tid = threadIdx.x;
    const int m0  = blockIdx.x * 64;
    const int bn  = blockIdx.y;            // 0..17
    const int grp = bn / 6;
    const int n0  = (bn - grp * 6) * 64;

    const float* W0 = (grp == 0) ? dt_w :
                      (grp == 1) ? g_GBp[0] : g_GCp[0];
    const float* W1 = (grp == 1) ? g_GBp[1] : g_GCp[1];
    const float* W2 = (grp == 1) ? g_GBp[2] : g_GCp[2];
    const bool sum3 = (grp != 0);

    const int loadRow = tid >> 2;
    const int loadCol = (tid & 3) << 2;
    const float* Ap = x + (m0 + loadRow) * 384 + loadCol;
    const int woff0 = (n0 + loadRow) * 384 + loadCol;

    float4 aR = *(const float4*)Ap;
    float4 wR;
    if (sum3) {
        const float4 p0 = *(const float4*)(W0 + woff0);
        const float4 p1 = *(const float4*)(W1 + woff0);
        const float4 p2 = *(const float4*)(W2 + woff0);
        wR = make_float4(p0.x + p1.x + p2.x, p0.y + p1.y + p2.y,
                         p0.z + p1.z + p2.z, p0.w + p1.w + p2.w);
    } else {
        wR = *(const float4*)(W0 + woff0);
    }

    float acc[4][4];
#pragma unroll
    for (int i = 0; i < 4; i++)
#pragma unroll
        for (int j = 0; j < 4; j++) acc[i][j] = 0.f;

    const int tx = tid & 15;
    const int ty = tid >> 4;

    for (int kt = 0; kt < 24; ++kt) {
        As[loadCol + 0][loadRow] = aR.x;
        As[loadCol + 1][loadRow] = aR.y;
        As[loadCol + 2][loadRow] = aR.z;
        As[loadCol + 3][loadRow] = aR.w;
        Bs[loadCol + 0][loadRow] = wR.x;
        Bs[loadCol + 1][loadRow] = wR.y;
        Bs[loadCol + 2][loadRow] = wR.z;
        Bs[loadCol + 3][loadRow] = wR.w;
        __syncthreads();

        if (kt < 23) {
            const int off = (kt + 1) * 16;
            aR = *(const float4*)(Ap + off);
            if (sum3) {
                const float4 p0 = *(const float4*)(W0 + woff0 + off);
                const float4 p1 = *(const float4*)(W1 + woff0 + off);
                const float4 p2 = *(const float4*)(W2 + woff0 + off);
                wR = make_float4(p0.x + p1.x + p2.x, p0.y + p1.y + p2.y,
                                 p0.z + p1.z + p2.z, p0.w + p1.w + p2.w);
            } else {
                wR = *(const float4*)(W0 + woff0 + off);
            }
        }

#pragma unroll
        for (int k = 0; k < 16; ++k) {
            float4 av = *(const float4*)&As[k][ty << 2];
            float4 bv = *(const float4*)&Bs[k][tx << 2];
            float a[4] = {av.x, av.y, av.z, av.w};
            float b[4] = {bv.x, bv.y, bv.z, bv.w};
#pragma unroll
            for (int i = 0; i < 4; i++)
#pragma unroll
                for (int j = 0; j < 4; j++)
                    acc[i][j] = fmaf(a[i], b[j], acc[i][j]);
        }
        __syncthreads();
    }

    if (grp == 0) {
        // dt epilogue: softplus + pack (dt, dt*u) into g_SC[b][d][l]
        const int b = (m0 >= 384);
#pragma unroll
        for (int i = 0; i < 4; i++) {
            const int m = m0 + (ty << 2) + i;
            const int l = m - b * 384;
#pragma unroll
            for (int j = 0; j < 4; j++) {
                const int n = n0 + (tx << 2) + j;      // channel d
                float v = acc[i][j] + dt_b[n];
                const float dt = fmaxf(v, 0.f) + log1pf(expf(-fabsf(v)));
                const int idx = (b * 384 + n) * 384 + l;
                const float u = g_U[idx];
                *(float2*)&g_SC[idx] = make_float2(dt, dt * u);
            }
        }
    } else {
        float* Cc = (grp == 1) ? g_BM : g_CM;
#pragma unroll
        for (int i = 0; i < 4; i++) {
            const int m = m0 + (ty << 2) + i;
#pragma unroll
            for (int j = 0; j < 4; j++)
                Cc[m * 384 + n0 + (tx << 2) + j] = acc[i][j];
        }
    }
}

// ---------------------------------------------------------------------------
// SCAN v5 (proven, unchanged): grid 384, block 384. CTA = 2 channels.
// ---------------------------------------------------------------------------
#define TL 48

__global__ __launch_bounds__(384) void scan_kernel(
    const float* __restrict__ A_log,
    float* __restrict__ out)
{
    __shared__ float  part[2][TL][49];
    __shared__ float4 scbuf[2][2][TL];

    const int tid  = threadIdx.x;
    const int lane = tid & 31;
    const int ch   = tid >= 192;
    const int s2   = tid - ch * 192;
    const int wid6 = (tid >> 5) - ch * 6;

    const int pid   = blockIdx.x;
    const int b     = pid / 192;
    const int dbase = (pid - b * 192) * 2;
    const int d     = dbase + ch;

    const float2 a = ((const float2*)(A_log + d * 384))[s2];
    const float A2x = -ex2f(a.x * LOG2E) * LOG2E;
    const float A2y = -ex2f(a.y * LOG2E) * LOG2E;
    const float2 bm = ((const float2*)(g_BM + (b * 384 + d) * 384))[s2];
    float hx = 0.f, hy = 0.f;

    const float4* scp0 = g_SC + (b * 384 + dbase) * 384;
    const float2* Cb2  = (const float2*)(g_CM + b * 147456) + s2;

    if (tid < 96) {
        const int c = tid / TL, li = tid - c * TL;
        scbuf[0][c][li] = __ldg(scp0 + c * 384 + li);
    }
    float2 C0 = __ldg(Cb2);
    float2 C1 = __ldg(Cb2 + 192);
    __syncthreads();

    float accP = 0.f;

    for (int tile = 0; tile < 8; ++tile) {
        const int lbase = tile * TL;
        const int buf   = tile & 1;

#pragma unroll 6
        for (int i = 0; i < TL; ++i) {
            const int l = lbase + i;
            const float4 sc = scbuf[buf][ch][i];
            const float2 Cv = C0;
            C0 = C1;
            const int lpf = (l + 2 < 384) ? (l + 2) : 383;
            C1 = __ldg(Cb2 + lpf * 192);

            const float e0 = ex2f(sc.x * A2x);
            hx = fmaf(e0, hx, sc.y * bm.x);
            const float e1 = ex2f(sc.x * A2y);
            hy = fmaf(e1, hy, sc.y * bm.y);
            const float acc = fmaf(hy, Cv.y, hx * Cv.x);

            if (i > 0) {
                accP += __shfl_xor_sync(0xffffffffu, accP, 16);
                accP += __shfl_xor_sync(0xffffffffu, accP, 8);
                if (lane < 8) part[ch][i - 1][wid6 * 8 + lane] = accP;
            }
            accP = acc;
        }
        accP += __shfl_xor_sync(0xffffffffu, accP, 16);
        accP += __shfl_xor_sync(0xffffffffu, accP, 8);
        if (lane < 8) part[ch][TL - 1][wid6 * 8 + lane] = accP;
        __syncthreads();

        if (tid < 96) {
            const int c  = tid / TL;
            const int li = tid - c * TL;
            const float* p = part[c][li];
            float t0 = 0.f, t1 = 0.f, t2 = 0.f, t3 = 0.f;
#pragma unroll
            for (int j = 0; j < 48; j += 4) {
                t0 += p[j]; t1 += p[j + 1]; t2 += p[j + 2]; t3 += p[j + 3];
            }
            const int l = lbase + li;
            float y = (t0 + t1) + (t2 + t3);
            y += scbuf[buf][c][li].z;
            out[(size_t)b * 147456 + (size_t)l * 384 + dbase + c] = y;
        } else if (tid < 192 && tile < 7) {
            const int t2i = tid - 96;
            const int c = t2i / TL, li = t2i - c * TL;
            scbuf[buf ^ 1][c][li] = __ldg(scp0 + c * 384 + lbase + TL + li);
        }
        __syncthreads();
    }
}

// ---------------------------------------------------------------------------
extern "C" void kernel_launch(void* const* d_in, const int* in_sizes, int n_in,
                              void* d_out, int out_size)
{
    const float* x      = (const float*)d_in[0];
    const float* A_log  = (const float*)d_in[1];
    const float* Dvec   = (const float*)d_in[2];
    const float* dt_w   = (const float*)d_in[3];
    const float* dt_b   = (const float*)d_in[4];
    const float* B_w    = (const float*)d_in[5];
    const float* C_w    = (const float*)d_in[6];
    const float* conv_w = (const float*)d_in[7];
    const float* conv_b = (const float*)d_in[8];
    float* out = (float*)d_out;

    // G_B, G_C (split-K partials) + conv/silu
    prep_kernel<<<dim3(6, 13, 3), 256>>>(x, B_w, C_w, conv_w, conv_b, Dvec);
    // dt (softplus + pack), Bm, Cm in one launch
    main_gemm<<<dim3(12, 18), 256>>>(x, dt_w, dt_b);
    // Scan
    scan_kernel<<<384, 384>>>(A_log, out);
}

// round 12
// speedup vs baseline: 1.0701x; 1.0701x over previous
#include <cuda_runtime.h>

// ---------------------------------------------------------------------------
// MambaSSM: B=2, L=384, d_inner=384, d_state=384, dt_rank=384, d_conv=4
//
//   conv_u:  u = silu(causal_conv(x)+cb) -> g_U ; g_SC[..].z = u*D[d]
//            (depends only on x; runs first)
//   GEMM1:   dt = softplus(x @ dt_w^T + dt_b); epilogue packs
//            g_SC[b][d][l].xy = (dt, dt*u)  (reads g_U)
//            x_dbl = x @ B_w^T -> g_XDBL
//   GEMM2:   Bm = x_dbl @ B_w^T -> g_BM ; Cm = x_dbl @ C_w^T -> g_CM
//   SCAN v5 (proven, unchanged).
//
//   GEMM v12: 64x64 tiles, double-buffered smem (1 barrier per k-tile).
// ---------------------------------------------------------------------------

#define LOG2E 1.4426950408889634f

__device__ float  g_U   [768 * 384];
__device__ float  g_XDBL[768 * 384];
__device__ float  g_BM  [768 * 384];
__device__ float  g_CM  [768 * 384];
__device__ float4 g_SC  [768 * 384];   // (dt, dt*u, u*D, -)

__device__ __forceinline__ float ex2f(float x) {
    float y;
    asm("ex2.approx.ftz.f32 %0, %1;" : "=f"(y) : "f"(x));
    return y;
}

// ---------------------------------------------------------------------------
// conv_u: causal depthwise conv(4) + silu. Independent of the GEMMs.
// grid (24, 2), block 384 (thread = channel d), 16 l's per block.
// ---------------------------------------------------------------------------
__global__ __launch_bounds__(384) void conv_u_kernel(
    const float* __restrict__ x,
    const float* __restrict__ convw,
    const float* __restrict__ convb,
    const float* __restrict__ Dvec)
{
    const int d  = threadIdx.x;
    const int b  = blockIdx.y;
    const int l0 = blockIdx.x * 16;

    const float c0 = convw[d * 4 + 0];
    const float c1 = convw[d * 4 + 1];
    const float c2 = convw[d * 4 + 2];
    const float c3 = convw[d * 4 + 3];
    const float cb = convb[d];
    const float Dd = Dvec[d];

    const float* xb = x + b * 147456 + d;
    float* up  = g_U + (b * 384 + d) * 384;
    float* scz = (float*)(g_SC + (b * 384 + d) * 384) + 2;

    float w0 = (l0 >= 3) ? xb[(l0 - 3) * 384] : 0.f;
    float w1 = (l0 >= 2) ? xb[(l0 - 2) * 384] : 0.f;
    float w2 = (l0 >= 1) ? xb[(l0 - 1) * 384] : 0.f;

    for (int i = 0; i < 16; ++i) {
        const int l = l0 + i;
        const float w3 = xb[l * 384];
        float v = fmaf(w0, c0, fmaf(w1, c1, fmaf(w2, c2, fmaf(w3, c3, cb))));
        const float u = v / (1.f + expf(-v));      // silu
        up[l] = u;
        scz[l * 4] = u * Dd;
        w0 = w1; w1 = w2; w2 = w3;
    }
}

// ---------------------------------------------------------------------------
// Dual-output tiled SGEMM, double-buffered smem: C[m,n] = sum_k A[m,k]*W[n,k]
// phase 0: A=x, Wa=dt_w (softplus + SC pack), Wb=B_w (-> g_XDBL)
// phase 1: A=g_XDBL, Wa=B_w (-> g_BM), Wb=C_w (-> g_CM)
// ---------------------------------------------------------------------------
__global__ __launch_bounds__(256) void gemm_dual(
    const float* __restrict__ A_ext,
    const float* __restrict__ Wa,
    const float* __restrict__ Wb,
    const float* __restrict__ bias,
    int phase)
{
    __shared__ float As[2][16][64];
    __shared__ float Bs[2][16][64];

    const float* A  = (phase == 0) ? A_ext : g_XDBL;

    const int tid = threadIdx.x;
    const int m0  = blockIdx.x * 64;
    const int bn  = blockIdx.y;            // 0..11
    const bool second = (bn >= 6);
    const float* W = second ? Wb : Wa;
    const bool doAct = (phase == 0) && !second;
    const int n0 = (second ? bn - 6 : bn) * 64;

    const int loadRow = tid >> 2;          // 0..63
    const int loadCol = (tid & 3) << 2;    // 0,4,8,12
    const float* Ap = A + (m0 + loadRow) * 384 + loadCol;
    const float* Wp = W + (n0 + loadRow) * 384 + loadCol;

    float4 aR = *(const float4*)Ap;
    float4 wR = *(const float4*)Wp;

    // store k-tile 0 into buffer 0
    As[0][loadCol + 0][loadRow] = aR.x;
    As[0][loadCol + 1][loadRow] = aR.y;
    As[0][loadCol + 2][loadRow] = aR.z;
    As[0][loadCol + 3][loadRow] = aR.w;
    Bs[0][loadCol + 0][loadRow] = wR.x;
    Bs[0][loadCol + 1][loadRow] = wR.y;
    Bs[0][loadCol + 2][loadRow] = wR.z;
    Bs[0][loadCol + 3][loadRow] = wR.w;
    __syncthreads();

    float acc[4][4];
#pragma unroll
    for (int i = 0; i < 4; i++)
#pragma unroll
        for (int j = 0; j < 4; j++) acc[i][j] = 0.f;

    const int tx = tid & 15;
    const int ty = tid >> 4;

    for (int kt = 0; kt < 24; ++kt) {
        const int cur = kt & 1;

        if (kt < 23) {   // issue next tile's loads early (latency cover)
            aR = *(const float4*)(Ap + (kt + 1) * 16);
            wR = *(const float4*)(Wp + (kt + 1) * 16);
        }

#pragma unroll
        for (int k = 0; k < 16; ++k) {
            float4 av = *(const float4*)&As[cur][k][ty << 2];
            float4 bv = *(const float4*)&Bs[cur][k][tx << 2];
            float a[4] = {av.x, av.y, av.z, av.w};
            float b[4] = {bv.x, bv.y, bv.z, bv.w};
#pragma unroll
            for (int i = 0; i < 4; i++)
#pragma unroll
                for (int j = 0; j < 4; j++)
                    acc[i][j] = fmaf(a[i], b[j], acc[i][j]);
        }

        if (kt < 23) {   // fill the other buffer; ONE barrier per tile
            const int nxt = cur ^ 1;
            As[nxt][loadCol + 0][loadRow] = aR.x;
            As[nxt][loadCol + 1][loadRow] = aR.y;
            As[nxt][loadCol + 2][loadRow] = aR.z;
            As[nxt][loadCol + 3][loadRow] = aR.w;
            Bs[nxt][loadCol + 0][loadRow] = wR.x;
            Bs[nxt][loadCol + 1][loadRow] = wR.y;
            Bs[nxt][loadCol + 2][loadRow] = wR.z;
            Bs[nxt][loadCol + 3][loadRow] = wR.w;
            __syncthreads();
        }
    }

    if (doAct) {
        // dt epilogue: softplus, read u, pack (dt, dt*u) into g_SC
        const int b = (m0 >= 384);
#pragma unroll
        for (int i = 0; i < 4; i++) {
            const int m = m0 + (ty << 2) + i;
            const int l = m - b * 384;
#pragma unroll
            for (int j = 0; j < 4; j++) {
                const int n = n0 + (tx << 2) + j;      // channel d
                float v = acc[i][j] + bias[n];
                const float dt = fmaxf(v, 0.f) + log1pf(expf(-fabsf(v)));
                const int idx = (b * 384 + n) * 384 + l;
                const float u = g_U[idx];
                *(float2*)&g_SC[idx] = make_float2(dt, dt * u);
            }
        }
    } else {
        float* Cc = (phase == 0) ? g_XDBL : (second ? g_CM : g_BM);
#pragma unroll
        for (int i = 0; i < 4; i++) {
            const int m = m0 + (ty << 2) + i;
#pragma unroll
            for (int j = 0; j < 4; j++)
                Cc[m * 384 + n0 + (tx << 2) + j] = acc[i][j];
        }
    }
}

// ---------------------------------------------------------------------------
// SCAN v5 (proven, unchanged): grid 384, block 384. CTA = 2 channels.
// ---------------------------------------------------------------------------
#define TL 48

__global__ __launch_bounds__(384) void scan_kernel(
    const float* __restrict__ A_log,
    float* __restrict__ out)
{
    __shared__ float  part[2][TL][49];
    __shared__ float4 scbuf[2][2][TL];

    const int tid  = threadIdx.x;
    const int lane = tid & 31;
    const int ch   = tid >= 192;
    const int s2   = tid - ch * 192;
    const int wid6 = (tid >> 5) - ch * 6;

    const int pid   = blockIdx.x;
    const int b     = pid / 192;
    const int dbase = (pid - b * 192) * 2;
    const int d     = dbase + ch;

    const float2 a = ((const float2*)(A_log + d * 384))[s2];
    const float A2x = -ex2f(a.x * LOG2E) * LOG2E;
    const float A2y = -ex2f(a.y * LOG2E) * LOG2E;
    const float2 bm = ((const float2*)(g_BM + (b * 384 + d) * 384))[s2];
    float hx = 0.f, hy = 0.f;

    const float4* scp0 = g_SC + (b * 384 + dbase) * 384;
    const float2* Cb2  = (const float2*)(g_CM + b * 147456) + s2;

    if (tid < 96) {
        const int c = tid / TL, li = tid - c * TL;
        scbuf[0][c][li] = __ldg(scp0 + c * 384 + li);
    }
    float2 C0 = __ldg(Cb2);
    float2 C1 = __ldg(Cb2 + 192);
    __syncthreads();

    float accP = 0.f;

    for (int tile = 0; tile < 8; ++tile) {
        const int lbase = tile * TL;
        const int buf   = tile & 1;

#pragma unroll 6
        for (int i = 0; i < TL; ++i) {
            const int l = lbase + i;
            const float4 sc = scbuf[buf][ch][i];
            const float2 Cv = C0;
            C0 = C1;
            const int lpf = (l + 2 < 384) ? (l + 2) : 383;
            C1 = __ldg(Cb2 + lpf * 192);

            const float e0 = ex2f(sc.x * A2x);
            hx = fmaf(e0, hx, sc.y * bm.x);
            const float e1 = ex2f(sc.x * A2y);
            hy = fmaf(e1, hy, sc.y * bm.y);
            const float acc = fmaf(hy, Cv.y, hx * Cv.x);

            if (i > 0) {
                accP += __shfl_xor_sync(0xffffffffu, accP, 16);
                accP += __shfl_xor_sync(0xffffffffu, accP, 8);
                if (lane < 8) part[ch][i - 1][wid6 * 8 + lane] = accP;
            }
            accP = acc;
        }
        accP += __shfl_xor_sync(0xffffffffu, accP, 16);
        accP += __shfl_xor_sync(0xffffffffu, accP, 8);
        if (lane < 8) part[ch][TL - 1][wid6 * 8 + lane] = accP;
        __syncthreads();

        if (tid < 96) {
            const int c  = tid / TL;
            const int li = tid - c * TL;
            const float* p = part[c][li];
            float t0 = 0.f, t1 = 0.f, t2 = 0.f, t3 = 0.f;
#pragma unroll
            for (int j = 0; j < 48; j += 4) {
                t0 += p[j]; t1 += p[j + 1]; t2 += p[j + 2]; t3 += p[j + 3];
            }
            const int l = lbase + li;
            float y = (t0 + t1) + (t2 + t3);
            y += scbuf[buf][c][li].z;
            out[(size_t)b * 147456 + (size_t)l * 384 + dbase + c] = y;
        } else if (tid < 192 && tile < 7) {
            const int t2i = tid - 96;
            const int c = t2i / TL, li = t2i - c * TL;
            scbuf[buf ^ 1][c][li] = __ldg(scp0 + c * 384 + lbase + TL + li);
        }
        __syncthreads();
    }
}

// ---------------------------------------------------------------------------
extern "C" void kernel_launch(void* const* d_in, const int* in_sizes, int n_in,
                              void* d_out, int out_size)
{
    const float* x      = (const float*)d_in[0];
    const float* A_log  = (const float*)d_in[1];
    const float* Dvec   = (const float*)d_in[2];
    const float* dt_w   = (const float*)d_in[3];
    const float* dt_b   = (const float*)d_in[4];
    const float* B_w    = (const float*)d_in[5];
    const float* C_w    = (const float*)d_in[6];
    const float* conv_w = (const float*)d_in[7];
    const float* conv_b = (const float*)d_in[8];
    float* out = (float*)d_out;

    // conv/silu first (independent of GEMMs)
    conv_u_kernel<<<dim3(24, 2), 384>>>(x, conv_w, conv_b, Dvec);
    // GEMM1: dt (softplus + SC pack) + x_dbl
    gemm_dual<<<dim3(12, 12), 256>>>(x, dt_w, B_w, dt_b, 0);
    // GEMM2: Bm + Cm
    gemm_dual<<<dim3(12, 12), 256>>>(x, B_w, C_w, nullptr, 1);
    // Scan
    scan_kernel<<<384, 384>>>(A_log, out);
}